// round 2
// baseline (speedup 1.0000x reference)
#include <cuda_runtime.h>

// LocalSpatialEncoding: enc = [rel(3), |rel|] -> (W1,BN,ReLU)[4] -> (W2,BN,ReLU)[8]
// B=8, N=16384, K=16, total points = 2,097,152. Output (B,N,K,8) fp32.
// Memory-bound: ~94 MB total traffic. One thread per point, BN folded into
// weights in shared memory per block.

#define LSE_EPS 1e-5f
#define B_ 8
#define N_ 16384
#define K_ 16
#define TOTAL (B_ * N_ * K_)   // 2097152
#define THREADS 256

__global__ void __launch_bounds__(THREADS)
lse_kernel(const float* __restrict__ coords,
           const float* __restrict__ nbr,
           const float* __restrict__ W1, const float* __restrict__ g1,
           const float* __restrict__ b1, const float* __restrict__ m1,
           const float* __restrict__ v1,
           const float* __restrict__ W2, const float* __restrict__ g2,
           const float* __restrict__ b2, const float* __restrict__ m2,
           const float* __restrict__ v2,
           float* __restrict__ out)
{
    // Fused (BN-folded) parameters in shared memory.
    __shared__ float sW1[16];   // [o][c], o<4, c<4
    __shared__ float st1[4];
    __shared__ float sW2[32];   // [o][c], o<8, c<4
    __shared__ float st2[8];

    int t = threadIdx.x;
    if (t < 16) {
        int o = t >> 2;
        float s = g1[o] * rsqrtf(v1[o] + LSE_EPS);
        sW1[t] = W1[t] * s;
        if ((t & 3) == 0) st1[o] = b1[o] - m1[o] * s;
    } else if (t < 48) {
        int i = t - 16;
        int o = i >> 2;
        float s = g2[o] * rsqrtf(v2[o] + LSE_EPS);
        sW2[i] = W2[i] * s;
        if ((i & 3) == 0) st2[o] = b2[o] - m2[o] * s;
    }
    __syncthreads();

    int p = blockIdx.x * THREADS + threadIdx.x;
    if (p >= TOTAL) return;

    int pn = p >> 4;            // b*N + n  (point row index)

    // neighbor coords: contiguous 12B per point -> coalesced across the warp
    const float* nb = nbr + (size_t)p * 3;
    float n0 = __ldg(nb + 0);
    float n1 = __ldg(nb + 1);
    float n2 = __ldg(nb + 2);

    // center coord: shared by 16 consecutive threads -> L1 broadcast
    const float* cp = coords + (size_t)pn * 3;
    float c0 = __ldg(cp + 0);
    float c1 = __ldg(cp + 1);
    float c2 = __ldg(cp + 2);

    float r0 = n0 - c0;
    float r1 = n1 - c1;
    float r2 = n2 - c2;
    float dist = sqrtf(fmaf(r0, r0, fmaf(r1, r1, r2 * r2)));

    // Layer 1: 4 outputs
    float h[4];
#pragma unroll
    for (int o = 0; o < 4; o++) {
        float acc = st1[o];
        acc = fmaf(r0,   sW1[o * 4 + 0], acc);
        acc = fmaf(r1,   sW1[o * 4 + 1], acc);
        acc = fmaf(r2,   sW1[o * 4 + 2], acc);
        acc = fmaf(dist, sW1[o * 4 + 3], acc);
        h[o] = fmaxf(acc, 0.0f);
    }

    // Layer 2: 8 outputs
    float y[8];
#pragma unroll
    for (int o = 0; o < 8; o++) {
        float acc = st2[o];
        acc = fmaf(h[0], sW2[o * 4 + 0], acc);
        acc = fmaf(h[1], sW2[o * 4 + 1], acc);
        acc = fmaf(h[2], sW2[o * 4 + 2], acc);
        acc = fmaf(h[3], sW2[o * 4 + 3], acc);
        y[o] = fmaxf(acc, 0.0f);
    }

    // 8 floats per point, 32B aligned -> two STG.128, fully coalesced
    float4* o4 = reinterpret_cast<float4*>(out) + (size_t)p * 2;
    o4[0] = make_float4(y[0], y[1], y[2], y[3]);
    o4[1] = make_float4(y[4], y[5], y[6], y[7]);
}

extern "C" void kernel_launch(void* const* d_in, const int* in_sizes, int n_in,
                              void* d_out, int out_size)
{
    const float* coords = (const float*)d_in[0];
    const float* nbr    = (const float*)d_in[1];
    const float* W1     = (const float*)d_in[2];
    const float* g1     = (const float*)d_in[3];
    const float* b1     = (const float*)d_in[4];
    const float* m1     = (const float*)d_in[5];
    const float* v1     = (const float*)d_in[6];
    const float* W2     = (const float*)d_in[7];
    const float* g2     = (const float*)d_in[8];
    const float* b2     = (const float*)d_in[9];
    const float* m2     = (const float*)d_in[10];
    const float* v2     = (const float*)d_in[11];
    float* out = (float*)d_out;

    int blocks = (TOTAL + THREADS - 1) / THREADS;   // 8192
    lse_kernel<<<blocks, THREADS>>>(coords, nbr, W1, g1, b1, m1, v1,
                                    W2, g2, b2, m2, v2, out);
}